// round 16
// baseline (speedup 1.0000x reference)
#include <cuda_runtime.h>
#include <cuda_bf16.h>
#include <cuda_fp16.h>
#include <cstdint>

// ---------------- problem constants ----------------
#define BB   64
#define NNN  197
#define CC   768
#define HHH  12
#define GHH  2
#define HRR  6
#define DD   64
#define TOTH 16
#define QKVN 1024
#define SCALE 0.125f
#define NT   4            // query rows per probs CTA
#define NPADR 208         // padded n rows in g_p
#define KPAD 224          // padded m (K dim of PV)
#define SPP  228          // padded row stride for S_s / L_s
#define MROWS (BB*NNN)    // 12608

// ---------------- device scratch ----------------
__device__ float g_q [BB*GHH*NNN*DD];
__device__ float g_k [BB*GHH*NNN*DD];
__device__ __half2 g_mw2[NNN*6*KPAD];         // mask weights: [n][hp][m224], hp=h/2 pairs

__device__ __half g_p  [BB*HHH*NPADR*KPAD];   // probs fp16 (K-pad zeroed)
__device__ __half g_vt [BB*HHH*DD*KPAD];      // V^T fp16  [bh][d][m]

// fp16 GEMM operands (single term)
__device__ __half g_x16[MROWS*CC];            // x fp16
__device__ __half g_a16[MROWS*CC];            // attention output fp16
__device__ __half g_qw16[QKVN*CC];            // qkv_w^T fp16  [N][K]
__device__ __half g_pw16[CC*CC];              // proj_w^T fp16 [N][K]

// ---------------- convert kernels ----------------
__global__ void tohalf_kernel(const float* __restrict__ src,
                              __half* __restrict__ dst, int n)
{
    int i = blockIdx.x*blockDim.x + threadIdx.x;
    if (i < n) dst[i] = __float2half(src[i]);
}

// transpose + convert: w is [K][N] row-major -> out [N][K] fp16
__global__ void wtrans_kernel(const float* __restrict__ w,
                              __half* __restrict__ dstT, int K, int N)
{
    int i = blockIdx.x*blockDim.x + threadIdx.x;
    if (i < K*N) {
        int k = i / N, n = i - k*N;
        dstT[(size_t)n*K + k] = __float2half(w[i]);
    }
}

// ---------------- MMA helpers ----------------
__device__ __forceinline__ void mma16816h(float* d,
    uint32_t a0, uint32_t a1, uint32_t a2, uint32_t a3,
    uint32_t b0, uint32_t b1)
{
    asm volatile(
        "mma.sync.aligned.m16n8k16.row.col.f32.f16.f16.f32 "
        "{%0,%1,%2,%3}, {%4,%5,%6,%7}, {%8,%9}, {%0,%1,%2,%3};"
        : "+f"(d[0]), "+f"(d[1]), "+f"(d[2]), "+f"(d[3])
        : "r"(a0), "r"(a1), "r"(a2), "r"(a3), "r"(b0), "r"(b1));
}

#define LDSM_X4(r0, r1, r2, r3, addr) \
    asm volatile("ldmatrix.sync.aligned.m8n8.x4.shared.b16 {%0,%1,%2,%3}, [%4];" \
        : "=r"(r0), "=r"(r1), "=r"(r2), "=r"(r3) : "r"(addr))

// ---------------- single-term fp16 GEMM, 3-stage cp.async ---------------------
// D = A*B^T (fp16 operands, fp32 accum). B stored [N][K] K-major.
// CTA 128x128, 8 warps (64x32 each), K-step 64, 3-stage cp.async pipeline.
// EPI==0: C = D + bias   EPI==1: scatter into g_q/g_k (fp32) and g_vt (fp16^T)
#define TGM 128
#define TGN 128
#define KS4 64
#define AST4 72                          // smem row stride fp16 (64 + 8 pad)
#define OP4_BYTES (TGM*AST4*2)           // 18432 per operand per stage
#define STG4_BYTES (2*OP4_BYTES)         // A + B per stage (36864)
#define NSTAGE 3
#define TG4_SMEM   (NSTAGE*STG4_BYTES)   // 110592 bytes

template<int EPI>
__global__ __launch_bounds__(256, 2)
void tgemm(const __half* __restrict__ A, const __half* __restrict__ Bw,
           const float* __restrict__ bias, float* __restrict__ C,
           int M, int Nc, int K)
{
    extern __shared__ char sm2[];
    const uint32_t smem_base = (uint32_t)__cvta_generic_to_shared(sm2);

    const int tid  = threadIdx.x;
    const int lane = tid & 31;
    const int warp = tid >> 5;
    const int mw   = warp >> 2;
    const int nw   = warp & 3;
    const int g    = lane >> 2;
    const int tig  = lane & 3;

    const int rowBase = blockIdx.y * TGM;
    const int colBase = blockIdx.x * TGN;

    const int nchunks = K / KS4;            // 12

    // ldmatrix lane address components
    const int lr      = lane & 7;
    const int aRowOff = ((lane >> 3) & 1) * 8 + lr;
    const int aKoff   = (lane >> 4) * 8;
    const int bTile   = (lane >> 4) & 1;
    const int bKoff   = ((lane >> 3) & 1) * 8;

    float acc[4][4][4];
    #pragma unroll
    for (int i = 0; i < 4; i++)
        #pragma unroll
        for (int j = 0; j < 4; j++)
            #pragma unroll
            for (int t = 0; t < 4; t++) acc[i][j][t] = 0.f;

    // load one chunk: 2 tiles x 128 rows x 128B = 2048 x 16B, 8 per thread
    auto issue = [&](int c) {
        int k0 = c * KS4;
        uint32_t buf = smem_base + (uint32_t)(c % NSTAGE) * STG4_BYTES;
        #pragma unroll
        for (int it = 0; it < 4; it++) {
            int u = tid + it*256;              // 0..1023
            int r = u >> 3, q = u & 7;
            int gr = rowBase + r;
            uint32_t ad = buf + (uint32_t)(r*(AST4*2) + q*16);
            const __half* srcA = A + (size_t)(gr < M ? gr : 0)*K + k0 + q*8;
            int nb = (gr < M) ? 16 : 0;
            asm volatile("cp.async.cg.shared.global [%0], [%1], 16, %2;"
                         :: "r"(ad), "l"(srcA), "r"(nb));
            uint32_t bd = ad + OP4_BYTES;
            const __half* srcB = Bw + (size_t)(colBase + r)*K + k0 + q*8;
            asm volatile("cp.async.cg.shared.global [%0], [%1], 16;"
                         :: "r"(bd), "l"(srcB));
        }
        asm volatile("cp.async.commit_group;" ::: "memory");
    };

    issue(0);
    issue(1);

    for (int c = 0; c < nchunks; c++) {
        if (c + 2 < nchunks) {
            issue(c + 2);
            asm volatile("cp.async.wait_group 2;" ::: "memory");
        } else if (c + 1 < nchunks) {
            asm volatile("cp.async.wait_group 1;" ::: "memory");
        } else {
            asm volatile("cp.async.wait_group 0;" ::: "memory");
        }
        __syncthreads();

        uint32_t As_u = smem_base + (uint32_t)(c % NSTAGE) * STG4_BYTES;
        uint32_t Bs_u = As_u + OP4_BYTES;

        #pragma unroll
        for (int kh = 0; kh < KS4; kh += 16) {
            uint32_t afr[4][4], bfr[4][2];
            #pragma unroll
            for (int i = 0; i < 4; i++) {
                uint32_t ad = As_u + (uint32_t)(((mw*64 + i*16 + aRowOff)*AST4 + kh + aKoff) * 2);
                LDSM_X4(afr[i][0], afr[i][1], afr[i][2], afr[i][3], ad);
            }
            #pragma unroll
            for (int p = 0; p < 2; p++) {
                uint32_t bd = Bs_u + (uint32_t)(((nw*32 + (2*p + bTile)*8 + lr)*AST4 + kh + bKoff) * 2);
                LDSM_X4(bfr[2*p][0], bfr[2*p][1], bfr[2*p+1][0], bfr[2*p+1][1], bd);
            }
            #pragma unroll
            for (int i = 0; i < 4; i++)
                #pragma unroll
                for (int j = 0; j < 4; j++)
                    mma16816h(acc[i][j], afr[i][0], afr[i][1], afr[i][2], afr[i][3],
                              bfr[j][0], bfr[j][1]);
        }
        __syncthreads();
    }

    #pragma unroll
    for (int i = 0; i < 4; i++) {
        #pragma unroll
        for (int half = 0; half < 2; half++) {
            int gr = rowBase + mw*64 + i*16 + g + half*8;
            if (gr >= M) continue;
            int bidx = 0, n = 0;
            if (EPI == 1) { bidx = gr / NNN; n = gr - bidx*NNN; }
            #pragma unroll
            for (int j = 0; j < 4; j++) {
                int gc = colBase + nw*32 + j*8 + tig*2;
                float2 v;
                v.x = acc[i][j][half*2 + 0] + bias[gc];
                v.y = acc[i][j][half*2 + 1] + bias[gc + 1];
                if (EPI == 0) {
                    *(float2*)(C + (size_t)gr*Nc + gc) = v;
                } else {
                    int t = gc >> 6, d = gc & 63;
                    if (t < GHH) {
                        *(float2*)(g_q + (((size_t)bidx*GHH + t)*NNN + n)*DD + d) = v;
                    } else if (t < 2*GHH) {
                        *(float2*)(g_k + (((size_t)bidx*GHH + (t-GHH))*NNN + n)*DD + d) = v;
                    } else {
                        int h = t - 2*GHH;
                        size_t bse = ((size_t)(bidx*HHH + h)*DD + d)*KPAD + n;
                        g_vt[bse]        = __float2half(v.x);
                        g_vt[bse + KPAD] = __float2half(v.y);
                    }
                }
            }
        }
    }
}

// ---------------- mask weights -> [n][hp][m224] half2, m-pad zeroed -----------
__global__ void mw_kernel(const float* __restrict__ masks,
                          const float* __restrict__ mproj,
                          const float* __restrict__ mbase)
{
    int idx = blockIdx.x * blockDim.x + threadIdx.x;   // n*KPAD + m
    if (idx >= NNN*KPAD) return;
    int n = idx / KPAD, m = idx - n*KPAD;
    float l0 = 0.f, l1 = 0.f, l2 = 0.f;
    bool valid = (m < NNN);
    if (valid) {
        size_t mi = ((size_t)n*NNN + m)*3;
        l0 = masks[mi + 0]; l1 = masks[mi + 1]; l2 = masks[mi + 2];
    }
    #pragma unroll
    for (int hp = 0; hp < 6; hp++) {
        float v0 = 0.f, v1 = 0.f;
        if (valid) {
            int h0 = hp*2, h1 = hp*2 + 1;
            v0 = l0*mproj[0*HHH + h0] + l1*mproj[1*HHH + h0] + l2*mproj[2*HHH + h0] + mbase[h0];
            v1 = l0*mproj[0*HHH + h1] + l1*mproj[1*HHH + h1] + l2*mproj[2*HHH + h1] + mbase[h1];
        }
        g_mw2[((size_t)n*6 + hp)*KPAD + m] = __floats2half2_rn(v0, v1);
    }
}

// ---------------- probs kernel: QK + HMMA head-mix + softmax -> g_p fp16 ------
#define PR_SMEM_FLOATS (NT*GHH*DD + NT*GHH*SPP + NT*HHH*SPP + 16)
#define PR_SMEM_BYTES  (PR_SMEM_FLOATS * 4)

__global__ __launch_bounds__(256, 4)
void attn_probs(const float* __restrict__ hpw, const float* __restrict__ hpb)
{
    extern __shared__ float sm[];
    float* q_s  = sm;
    float* S_s  = q_s + NT*GHH*DD;
    float* L_s  = S_s + NT*GHH*SPP;
    float* hb_s = L_s + NT*HHH*SPP;

    const int tid  = threadIdx.x;
    const int lane = tid & 31;
    const int warp = tid >> 5;
    const int r    = lane >> 2;
    const int tig  = lane & 3;
    const int b    = blockIdx.y;
    const int n0   = blockIdx.x * NT;
    const int nvalid = min(NT, NNN - n0);

    if (tid < 12) hb_s[tid] = hpb[tid];

    uint32_t wf[2][2];
    {
        int nn = r;
        #pragma unroll
        for (int j = 0; j < 2; j++) {
            int n = j*8 + nn;
            int k0 = tig*2;
            float w00 = (n < 12) ? hpw[k0*12 + n]     : 0.f;
            float w01 = (n < 12) ? hpw[(k0+1)*12 + n] : 0.f;
            __half2 h0 = __floats2half2_rn(w00, w01);
            wf[j][0] = *(uint32_t*)&h0;
            int k1 = k0 + 8;
            float w10 = (n < 12 && k1   < 12) ? hpw[k1*12 + n]     : 0.f;
            float w11 = (n < 12 && k1+1 < 12) ? hpw[(k1+1)*12 + n] : 0.f;
            __half2 h1 = __floats2half2_rn(w10, w11);
            wf[j][1] = *(uint32_t*)&h1;
        }
    }

    for (int i = tid; i < NT*GHH*DD; i += 256) {
        int nt = i / (GHH*DD), rem = i % (GHH*DD);
        int g = rem / DD, d = rem % DD;
        q_s[(nt*GHH + g)*DD + d] = (nt < nvalid)
            ? g_q[(((size_t)b*GHH + g)*NNN + (n0 + nt))*DD + d] : 0.f;
    }
    __syncthreads();

    // Phase 1a: S (fp32), m padded to 224 with zeros
    for (int idx = tid; idx < KPAD*GHH; idx += 256) {
        int m = idx >> 1, g = idx & 1;
        float accm[NT];
        #pragma unroll
        for (int nt = 0; nt < NT; nt++) accm[nt] = 0.f;
        if (m < NNN) {
            const float4* kp = (const float4*)(g_k + (((size_t)b*GHH + g)*NNN + m)*DD);
            #pragma unroll
            for (int t = 0; t < 16; t++) {
                float4 kv = kp[t];
                #pragma unroll
                for (int nt = 0; nt < NT; nt++) {
                    float4 qv = *(const float4*)&q_s[(nt*GHH + g)*DD + t*4];
                    accm[nt] = fmaf(qv.x, kv.x, accm[nt]);
                    accm[nt] = fmaf(qv.y, kv.y, accm[nt]);
                    accm[nt] = fmaf(qv.z, kv.z, accm[nt]);
                    accm[nt] = fmaf(qv.w, kv.w, accm[nt]);
                }
            }
        }
        #pragma unroll
        for (int nt = 0; nt < NT; nt++)
            S_s[(nt*GHH + g)*SPP + m] = accm[nt] * SCALE;
    }
    __syncthreads();

    // Phase 1b: relu(s*mw) fragments -> 2 HMMA per (nt, m16-tile)
    // mw loads from [n][hp][m224] half2 layout: fully coalesced across r lanes
    for (int u = warp; u < NT*(KPAD/16); u += 8) {
        int nt = u / (KPAD/16), mt = u - nt*(KPAD/16);
        int n = n0 + nt; if (n >= NNN) n = NNN - 1;
        int m0 = mt*16 + r, m1 = m0 + 8;

        float s0a = S_s[(nt*GHH + 0)*SPP + m0];
        float s1a = S_s[(nt*GHH + 1)*SPP + m0];
        float s0b = S_s[(nt*GHH + 0)*SPP + m1];
        float s1b = S_s[(nt*GHH + 1)*SPP + m1];
        float slo_a = (tig < 3) ? s0a : s1a;
        float slo_b = (tig < 3) ? s0b : s1b;

        const __half2* mwp = g_mw2 + (size_t)n*6*KPAD;
        float2 mlo_a = __half22float2(mwp[(size_t)tig*KPAD + m0]);
        float2 mlo_b = __half22float2(mwp[(size_t)tig*KPAD + m1]);
        float2 mhi_a = make_float2(0.f, 0.f), mhi_b = make_float2(0.f, 0.f);
        if (tig < 2) {
            mhi_a = __half22float2(mwp[(size_t)(4 + tig)*KPAD + m0]);
            mhi_b = __half22float2(mwp[(size_t)(4 + tig)*KPAD + m1]);
        }

        __half2 a0h = __floats2half2_rn(fmaxf(slo_a*mlo_a.x, 0.f), fmaxf(slo_a*mlo_a.y, 0.f));
        __half2 a1h = __floats2half2_rn(fmaxf(slo_b*mlo_b.x, 0.f), fmaxf(slo_b*mlo_b.y, 0.f));
        __half2 a2h = __floats2half2_rn(fmaxf(s1a*mhi_a.x, 0.f),  fmaxf(s1a*mhi_a.y, 0.f));
        __half2 a3h = __floats2half2_rn(fmaxf(s1b*mhi_b.x, 0.f),  fmaxf(s1b*mhi_b.y, 0.f));
        uint32_t a0 = *(uint32_t*)&a0h, a1 = *(uint32_t*)&a1h;
        uint32_t a2 = *(uint32_t*)&a2h, a3 = *(uint32_t*)&a3h;

        float c0[4] = {0.f,0.f,0.f,0.f};
        float c1[4] = {0.f,0.f,0.f,0.f};
        mma16816h(c0, a0, a1, a2, a3, wf[0][0], wf[0][1]);
        mma16816h(c1, a0, a1, a2, a3, wf[1][0], wf[1][1]);

        {
            int hp = tig*2;
            float* Lb = &L_s[(nt*HHH + hp)*SPP];
            Lb[m0]        = c0[0] + hb_s[hp];
            Lb[SPP + m0]  = c0[1] + hb_s[hp+1];
            Lb[m1]        = c0[2] + hb_s[hp];
            Lb[SPP + m1]  = c0[3] + hb_s[hp+1];
        }
        if (tig < 2) {
            int hp = 8 + tig*2;
            float* Lb = &L_s[(nt*HHH + hp)*SPP];
            Lb[m0]        = c1[0] + hb_s[hp];
            Lb[SPP + m0]  = c1[1] + hb_s[hp+1];
            Lb[m1]        = c1[2] + hb_s[hp];
            Lb[SPP + m1]  = c1[3] + hb_s[hp+1];
        }
    }
    __syncthreads();

    // Phase 2: softmax over m, write fp16 probs (K-pad zeroed)
    for (int pair = warp; pair < NT*HHH; pair += 8) {
        int nt = pair / HHH, hp = pair - nt*HHH;
        float* row = &L_s[pair*SPP];
        float mx = -1e30f;
        for (int m = lane; m < NNN; m += 32) mx = fmaxf(mx, row[m]);
        #pragma unroll
        for (int off = 16; off > 0; off >>= 1)
            mx = fmaxf(mx, __shfl_xor_sync(0xffffffffu, mx, off));
        float sum = 0.f;
        for (int m = lane; m < NNN; m += 32) {
            float e = __expf(row[m] - mx);
            row[m] = e;
            sum += e;
        }
        #pragma unroll
        for (int off = 16; off > 0; off >>= 1)
            sum += __shfl_xor_sync(0xffffffffu, sum, off);
        float inv = 1.f / sum;

        __half* op = g_p + ((size_t)(b*HHH + hp)*NPADR + (n0 + nt))*KPAD;
        #pragma unroll
        for (int i = 0; i < KPAD/32; i++) {
            int m = lane + i*32;
            float val = (m < NNN) ? row[m]*inv : 0.f;
            op[m] = __float2half(val);
        }
    }
}

// ---------------- PV kernel (single V term, unchanged) ------------------------
#define PST 40
#define PV_ABYTES (NPADR*PST*2)
#define PV_BBYTES (DD*PST*2)
#define PV_STAGE  (PV_ABYTES + PV_BBYTES)
#define PV_SMEM   (2*PV_STAGE)

__global__ __launch_bounds__(256, 3)
void pv_kernel()
{
    extern __shared__ char psm[];
    const uint32_t sbase = (uint32_t)__cvta_generic_to_shared(psm);
    __half* smh = (__half*)psm;

    const int tid  = threadIdx.x;
    const int lane = tid & 31;
    const int warp = tid >> 5;
    const int bh   = blockIdx.x;
    const int b    = bh / HHH;
    const int h    = bh - b*HHH;

    const __half* Ap = g_p  + (size_t)bh*NPADR*KPAD;
    const __half* Bp = g_vt + (size_t)bh*DD*KPAD;

    float acc[13][4];
    #pragma unroll
    for (int t = 0; t < 13; t++)
        #pragma unroll
        for (int c = 0; c < 4; c++) acc[t][c] = 0.f;

    const int NST = KPAD/32;               // 7 stages

    auto issue = [&](int s) {
        int k0 = s * 32;
        uint32_t buf = sbase + (uint32_t)(s & 1) * PV_STAGE;
        #pragma unroll
        for (int it = 0; it < 4; it++) {
            int c = tid + it*256;
            if (c < NPADR*4) {
                int r = c >> 2, q = c & 3;
                uint32_t ad = buf + (uint32_t)(r*(PST*2) + q*16);
                asm volatile("cp.async.cg.shared.global [%0], [%1], 16;"
                             :: "r"(ad), "l"(Ap + (size_t)r*KPAD + k0 + q*8));
            }
        }
        {
            int r = tid >> 2, q = tid & 3;
            uint32_t bd = buf + PV_ABYTES + (uint32_t)(r*(PST*2) + q*16);
            asm volatile("cp.async.cg.shared.global [%0], [%1], 16;"
                         :: "r"(bd), "l"(Bp + (size_t)r*KPAD + k0 + q*8));
        }
        asm volatile("cp.async.commit_group;" ::: "memory");
    };

    issue(0);

    for (int s = 0; s < NST; s++) {
        if (s + 1 < NST) {
            issue(s + 1);
            asm volatile("cp.async.wait_group 1;" ::: "memory");
        } else {
            asm volatile("cp.async.wait_group 0;" ::: "memory");
        }
        __syncthreads();

        const __half* As = smh + (size_t)(s & 1) * (PV_STAGE/2);
        const __half* Bs = As + PV_ABYTES/2;

        #pragma unroll
        for (int kh = 0; kh < 32; kh += 16) {
            const __half* pb = Bs + (warp*8 + (lane>>2))*PST + kh + (lane&3)*2;
            uint32_t b0 = *(const uint32_t*)(pb);
            uint32_t b1 = *(const uint32_t*)(pb + 8);
            #pragma unroll
            for (int t = 0; t < 13; t++) {
                const __half* pa = As + (t*16 + (lane>>2))*PST + kh + (lane&3)*2;
                uint32_t a0 = *(const uint32_t*)(pa);
                uint32_t a1 = *(const uint32_t*)(pa + 8*PST);
                uint32_t a2 = *(const uint32_t*)(pa + 8);
                uint32_t a3 = *(const uint32_t*)(pa + 8*PST + 8);
                mma16816h(acc[t], a0, a1, a2, a3, b0, b1);
            }
        }
        __syncthreads();
    }

    // epilogue: write fp16 attention output (feeds tgemm<0>)
    const int ch = h*DD + warp*8 + (lane&3)*2;
    #pragma unroll
    for (int t = 0; t < 13; t++) {
        #pragma unroll
        for (int half = 0; half < 2; half++) {
            int ntok = t*16 + (lane>>2) + half*8;
            if (ntok >= NNN) continue;
            size_t off = ((size_t)b*NNN + ntok)*CC + ch;
            __half2 hv;
            hv.x = __float2half(acc[t][half*2 + 0]);
            hv.y = __float2half(acc[t][half*2 + 1]);
            *(__half2*)(g_a16 + off) = hv;
        }
    }
}

// ---------------- launcher ----------------------------------------------------
extern "C" void kernel_launch(void* const* d_in, const int* in_sizes, int n_in,
                              void* d_out, int out_size)
{
    const float* x         = (const float*)d_in[0];
    const float* qkv_w     = (const float*)d_in[1];
    const float* qkv_b     = (const float*)d_in[2];
    const float* masks     = (const float*)d_in[3];
    const float* mask_proj = (const float*)d_in[4];
    const float* mask_base = (const float*)d_in[5];
    const float* hpw       = (const float*)d_in[6];
    const float* hpb       = (const float*)d_in[7];
    const float* proj_w    = (const float*)d_in[8];
    const float* proj_b    = (const float*)d_in[9];
    float* out             = (float*)d_out;

    void *x16_p, *a16_p, *qw16_p, *pw16_p;
    cudaGetSymbolAddress(&x16_p,  g_x16);
    cudaGetSymbolAddress(&a16_p,  g_a16);
    cudaGetSymbolAddress(&qw16_p, g_qw16);
    cudaGetSymbolAddress(&pw16_p, g_pw16);

    cudaFuncSetAttribute(attn_probs, cudaFuncAttributeMaxDynamicSharedMemorySize,
                         PR_SMEM_BYTES);
    cudaFuncSetAttribute(pv_kernel, cudaFuncAttributeMaxDynamicSharedMemorySize,
                         PV_SMEM);
    cudaFuncSetAttribute(tgemm<0>, cudaFuncAttributeMaxDynamicSharedMemorySize, TG4_SMEM);
    cudaFuncSetAttribute(tgemm<1>, cudaFuncAttributeMaxDynamicSharedMemorySize, TG4_SMEM);

    const int M = MROWS;
    const int MT = (M + TGM - 1)/TGM;

    // 0) fp16 conversions
    tohalf_kernel<<<(M*CC + 255)/256, 256>>>(x, (__half*)x16_p, M*CC);
    wtrans_kernel<<<(CC*QKVN + 255)/256, 256>>>(qkv_w, (__half*)qw16_p, CC, QKVN);
    wtrans_kernel<<<(CC*CC + 255)/256, 256>>>(proj_w, (__half*)pw16_p, CC, CC);
    // 1) QKV GEMM (fp16 single-term) + scatter (q,k fp32; v -> g_vt fp16^T)
    {
        dim3 grid(QKVN/TGN, MT);
        tgemm<1><<<grid, 256, TG4_SMEM>>>((const __half*)x16_p, (const __half*)qw16_p,
                                          qkv_b, nullptr, M, QKVN, CC);
    }
    // 2) mask weights (half2-pair transposed layout)
    mw_kernel<<<(NNN*KPAD + 255)/256, 256>>>(masks, mask_proj, mask_base);
    // 3) probs -> g_p fp16
    {
        dim3 grid((NNN + NT - 1)/NT, BB);
        attn_probs<<<grid, 256, PR_SMEM_BYTES>>>(hpw, hpb);
    }
    // 4) PV -> g_a16
    pv_kernel<<<BB*HHH, 256, PV_SMEM>>>();
    // 5) output projection (fp16 single-term)
    {
        dim3 grid(CC/TGN, MT);
        tgemm<0><<<grid, 256, TG4_SMEM>>>((const __half*)a16_p, (const __half*)pw16_p,
                                          proj_b, out, M, CC, CC);
    }
}

// round 17
// speedup vs baseline: 1.1086x; 1.1086x over previous
#include <cuda_runtime.h>
#include <cuda_bf16.h>
#include <cuda_fp16.h>
#include <cstdint>

// ---------------- problem constants ----------------
#define BB   64
#define NNN  197
#define CC   768
#define HHH  12
#define GHH  2
#define HRR  6
#define DD   64
#define TOTH 16
#define QKVN 1024
#define SCALE 0.125f
#define NT   8            // query rows per probs CTA (512 threads)
#define NPADR 208         // padded n rows in g_p
#define KPAD 224          // padded m (K dim of PV)
#define SPP  228          // padded row stride for S_s / L_s
#define MROWS (BB*NNN)    // 12608

// ---------------- device scratch ----------------
__device__ float g_q [BB*GHH*NNN*DD];
__device__ float g_k [BB*GHH*NNN*DD];
__device__ __half2 g_mw2[NNN*6*KPAD];         // mask weights: [n][hp][m224], hp=h/2 pairs

__device__ __half g_p  [BB*HHH*NPADR*KPAD];   // probs fp16 (K-pad zeroed)
__device__ __half g_vt [BB*HHH*DD*KPAD];      // V^T fp16  [bh][d][m]

// fp16 GEMM operands (single term)
__device__ __half g_x16[MROWS*CC];            // x fp16
__device__ __half g_a16[MROWS*CC];            // attention output fp16
__device__ __half g_qw16[QKVN*CC];            // qkv_w^T fp16  [N][K]
__device__ __half g_pw16[CC*CC];              // proj_w^T fp16 [N][K]

// ---------------- convert kernels ----------------
__global__ void tohalf_kernel(const float* __restrict__ src,
                              __half* __restrict__ dst, int n)
{
    int i = blockIdx.x*blockDim.x + threadIdx.x;
    if (i < n) dst[i] = __float2half(src[i]);
}

// transpose + convert: w is [K][N] row-major -> out [N][K] fp16
__global__ void wtrans_kernel(const float* __restrict__ w,
                              __half* __restrict__ dstT, int K, int N)
{
    int i = blockIdx.x*blockDim.x + threadIdx.x;
    if (i < K*N) {
        int k = i / N, n = i - k*N;
        dstT[(size_t)n*K + k] = __float2half(w[i]);
    }
}

// ---------------- MMA helpers ----------------
__device__ __forceinline__ void mma16816h(float* d,
    uint32_t a0, uint32_t a1, uint32_t a2, uint32_t a3,
    uint32_t b0, uint32_t b1)
{
    asm volatile(
        "mma.sync.aligned.m16n8k16.row.col.f32.f16.f16.f32 "
        "{%0,%1,%2,%3}, {%4,%5,%6,%7}, {%8,%9}, {%0,%1,%2,%3};"
        : "+f"(d[0]), "+f"(d[1]), "+f"(d[2]), "+f"(d[3])
        : "r"(a0), "r"(a1), "r"(a2), "r"(a3), "r"(b0), "r"(b1));
}

#define LDSM_X4(r0, r1, r2, r3, addr) \
    asm volatile("ldmatrix.sync.aligned.m8n8.x4.shared.b16 {%0,%1,%2,%3}, [%4];" \
        : "=r"(r0), "=r"(r1), "=r"(r2), "=r"(r3) : "r"(addr))

// ---------------- single-term fp16 GEMM, 2-stage cp.async (R15 proven) --------
#define TGM 128
#define TGN 128
#define KS4 64
#define AST4 72                          // smem row stride fp16 (64 + 8 pad)
#define OP4_BYTES (TGM*AST4*2)           // 18432 per operand per stage
#define STG4_BYTES (2*OP4_BYTES)         // A + B per stage
#define TG4_SMEM   (2*STG4_BYTES)        // 73728 bytes

template<int EPI>
__global__ __launch_bounds__(256, 2)
void tgemm(const __half* __restrict__ A, const __half* __restrict__ Bw,
           const float* __restrict__ bias, float* __restrict__ C,
           int M, int Nc, int K)
{
    extern __shared__ char sm2[];
    const uint32_t smem_base = (uint32_t)__cvta_generic_to_shared(sm2);

    const int tid  = threadIdx.x;
    const int lane = tid & 31;
    const int warp = tid >> 5;
    const int mw   = warp >> 2;
    const int nw   = warp & 3;
    const int g    = lane >> 2;
    const int tig  = lane & 3;

    const int rowBase = blockIdx.y * TGM;
    const int colBase = blockIdx.x * TGN;

    const int nchunks = K / KS4;            // 12

    const int lr      = lane & 7;
    const int aRowOff = ((lane >> 3) & 1) * 8 + lr;
    const int aKoff   = (lane >> 4) * 8;
    const int bTile   = (lane >> 4) & 1;
    const int bKoff   = ((lane >> 3) & 1) * 8;

    float acc[4][4][4];
    #pragma unroll
    for (int i = 0; i < 4; i++)
        #pragma unroll
        for (int j = 0; j < 4; j++)
            #pragma unroll
            for (int t = 0; t < 4; t++) acc[i][j][t] = 0.f;

    auto issue = [&](int c) {
        int k0 = c * KS4;
        uint32_t buf = smem_base + (uint32_t)(c & 1) * STG4_BYTES;
        #pragma unroll
        for (int it = 0; it < 4; it++) {
            int u = tid + it*256;              // 0..1023
            int r = u >> 3, q = u & 7;
            int gr = rowBase + r;
            uint32_t ad = buf + (uint32_t)(r*(AST4*2) + q*16);
            const __half* srcA = A + (size_t)(gr < M ? gr : 0)*K + k0 + q*8;
            int nb = (gr < M) ? 16 : 0;
            asm volatile("cp.async.cg.shared.global [%0], [%1], 16, %2;"
                         :: "r"(ad), "l"(srcA), "r"(nb));
            uint32_t bd = ad + OP4_BYTES;
            const __half* srcB = Bw + (size_t)(colBase + r)*K + k0 + q*8;
            asm volatile("cp.async.cg.shared.global [%0], [%1], 16;"
                         :: "r"(bd), "l"(srcB));
        }
        asm volatile("cp.async.commit_group;" ::: "memory");
    };

    issue(0);

    for (int c = 0; c < nchunks; c++) {
        if (c + 1 < nchunks) {
            issue(c + 1);
            asm volatile("cp.async.wait_group 1;" ::: "memory");
        } else {
            asm volatile("cp.async.wait_group 0;" ::: "memory");
        }
        __syncthreads();

        uint32_t As_u = smem_base + (uint32_t)(c & 1) * STG4_BYTES;
        uint32_t Bs_u = As_u + OP4_BYTES;

        #pragma unroll
        for (int kh = 0; kh < KS4; kh += 16) {
            uint32_t afr[4][4], bfr[4][2];
            #pragma unroll
            for (int i = 0; i < 4; i++) {
                uint32_t ad = As_u + (uint32_t)(((mw*64 + i*16 + aRowOff)*AST4 + kh + aKoff) * 2);
                LDSM_X4(afr[i][0], afr[i][1], afr[i][2], afr[i][3], ad);
            }
            #pragma unroll
            for (int p = 0; p < 2; p++) {
                uint32_t bd = Bs_u + (uint32_t)(((nw*32 + (2*p + bTile)*8 + lr)*AST4 + kh + bKoff) * 2);
                LDSM_X4(bfr[2*p][0], bfr[2*p][1], bfr[2*p+1][0], bfr[2*p+1][1], bd);
            }
            #pragma unroll
            for (int i = 0; i < 4; i++)
                #pragma unroll
                for (int j = 0; j < 4; j++)
                    mma16816h(acc[i][j], afr[i][0], afr[i][1], afr[i][2], afr[i][3],
                              bfr[j][0], bfr[j][1]);
        }
        __syncthreads();
    }

    #pragma unroll
    for (int i = 0; i < 4; i++) {
        #pragma unroll
        for (int half = 0; half < 2; half++) {
            int gr = rowBase + mw*64 + i*16 + g + half*8;
            if (gr >= M) continue;
            int bidx = 0, n = 0;
            if (EPI == 1) { bidx = gr / NNN; n = gr - bidx*NNN; }
            #pragma unroll
            for (int j = 0; j < 4; j++) {
                int gc = colBase + nw*32 + j*8 + tig*2;
                float2 v;
                v.x = acc[i][j][half*2 + 0] + bias[gc];
                v.y = acc[i][j][half*2 + 1] + bias[gc + 1];
                if (EPI == 0) {
                    *(float2*)(C + (size_t)gr*Nc + gc) = v;
                } else {
                    int t = gc >> 6, d = gc & 63;
                    if (t < GHH) {
                        *(float2*)(g_q + (((size_t)bidx*GHH + t)*NNN + n)*DD + d) = v;
                    } else if (t < 2*GHH) {
                        *(float2*)(g_k + (((size_t)bidx*GHH + (t-GHH))*NNN + n)*DD + d) = v;
                    } else {
                        int h = t - 2*GHH;
                        size_t bse = ((size_t)(bidx*HHH + h)*DD + d)*KPAD + n;
                        g_vt[bse]        = __float2half(v.x);
                        g_vt[bse + KPAD] = __float2half(v.y);
                    }
                }
            }
        }
    }
}

// ---------------- mask weights -> [n][hp][m224] half2, m-pad zeroed -----------
__global__ void mw_kernel(const float* __restrict__ masks,
                          const float* __restrict__ mproj,
                          const float* __restrict__ mbase)
{
    int idx = blockIdx.x * blockDim.x + threadIdx.x;   // n*KPAD + m
    if (idx >= NNN*KPAD) return;
    int n = idx / KPAD, m = idx - n*KPAD;
    float l0 = 0.f, l1 = 0.f, l2 = 0.f;
    bool valid = (m < NNN);
    if (valid) {
        size_t mi = ((size_t)n*NNN + m)*3;
        l0 = masks[mi + 0]; l1 = masks[mi + 1]; l2 = masks[mi + 2];
    }
    #pragma unroll
    for (int hp = 0; hp < 6; hp++) {
        float v0 = 0.f, v1 = 0.f;
        if (valid) {
            int h0 = hp*2, h1 = hp*2 + 1;
            v0 = l0*mproj[0*HHH + h0] + l1*mproj[1*HHH + h0] + l2*mproj[2*HHH + h0] + mbase[h0];
            v1 = l0*mproj[0*HHH + h1] + l1*mproj[1*HHH + h1] + l2*mproj[2*HHH + h1] + mbase[h1];
        }
        g_mw2[((size_t)n*6 + hp)*KPAD + m] = __floats2half2_rn(v0, v1);
    }
}

// ---------------- probs kernel: NT=8 rows, 512 threads ------------------------
#define PR_SMEM_FLOATS (NT*GHH*DD + NT*GHH*SPP + NT*HHH*SPP + 16)
#define PR_SMEM_BYTES  (PR_SMEM_FLOATS * 4)   // 106304

__global__ __launch_bounds__(512, 2)
void attn_probs(const float* __restrict__ hpw, const float* __restrict__ hpb)
{
    extern __shared__ float sm[];
    float* q_s  = sm;                          // [NT][GHH][DD]
    float* S_s  = q_s + NT*GHH*DD;             // [NT][GHH][SPP]
    float* L_s  = S_s + NT*GHH*SPP;            // [NT][HHH][SPP]
    float* hb_s = L_s + NT*HHH*SPP;            // [12]

    const int tid  = threadIdx.x;
    const int lane = tid & 31;
    const int warp = tid >> 5;                 // 0..15
    const int r    = lane >> 2;
    const int tig  = lane & 3;
    const int b    = blockIdx.y;
    const int n0   = blockIdx.x * NT;
    const int nvalid = min(NT, NNN - n0);

    if (tid < 12) hb_s[tid] = hpb[tid];

    uint32_t wf[2][2];
    {
        int nn = r;
        #pragma unroll
        for (int j = 0; j < 2; j++) {
            int n = j*8 + nn;
            int k0 = tig*2;
            float w00 = (n < 12) ? hpw[k0*12 + n]     : 0.f;
            float w01 = (n < 12) ? hpw[(k0+1)*12 + n] : 0.f;
            __half2 h0 = __floats2half2_rn(w00, w01);
            wf[j][0] = *(uint32_t*)&h0;
            int k1 = k0 + 8;
            float w10 = (n < 12 && k1   < 12) ? hpw[k1*12 + n]     : 0.f;
            float w11 = (n < 12 && k1+1 < 12) ? hpw[(k1+1)*12 + n] : 0.f;
            __half2 h1 = __floats2half2_rn(w10, w11);
            wf[j][1] = *(uint32_t*)&h1;
        }
    }

    for (int i = tid; i < NT*GHH*DD; i += 512) {
        int nt = i / (GHH*DD), rem = i % (GHH*DD);
        int g = rem / DD, d = rem % DD;
        q_s[(nt*GHH + g)*DD + d] = (nt < nvalid)
            ? g_q[(((size_t)b*GHH + g)*NNN + (n0 + nt))*DD + d] : 0.f;
    }
    __syncthreads();

    // Phase 1a: S (fp32), m padded to 224 with zeros
    for (int idx = tid; idx < KPAD*GHH; idx += 512) {
        int m = idx >> 1, g = idx & 1;
        float accm[NT];
        #pragma unroll
        for (int nt = 0; nt < NT; nt++) accm[nt] = 0.f;
        if (m < NNN) {
            const float4* kp = (const float4*)(g_k + (((size_t)b*GHH + g)*NNN + m)*DD);
            #pragma unroll
            for (int t = 0; t < 16; t++) {
                float4 kv = kp[t];
                #pragma unroll
                for (int nt = 0; nt < NT; nt++) {
                    float4 qv = *(const float4*)&q_s[(nt*GHH + g)*DD + t*4];
                    accm[nt] = fmaf(qv.x, kv.x, accm[nt]);
                    accm[nt] = fmaf(qv.y, kv.y, accm[nt]);
                    accm[nt] = fmaf(qv.z, kv.z, accm[nt]);
                    accm[nt] = fmaf(qv.w, kv.w, accm[nt]);
                }
            }
        }
        #pragma unroll
        for (int nt = 0; nt < NT; nt++)
            S_s[(nt*GHH + g)*SPP + m] = accm[nt] * SCALE;
    }
    __syncthreads();

    // Phase 1b: relu(s*mw) fragments -> 2 HMMA per (nt, m16-tile)
    for (int u = warp; u < NT*(KPAD/16); u += 16) {
        int nt = u / (KPAD/16), mt = u - nt*(KPAD/16);
        int n = n0 + nt; if (n >= NNN) n = NNN - 1;
        int m0 = mt*16 + r, m1 = m0 + 8;

        float s0a = S_s[(nt*GHH + 0)*SPP + m0];
        float s1a = S_s[(nt*GHH + 1)*SPP + m0];
        float s0b = S_s[(nt*GHH + 0)*SPP + m1];
        float s1b = S_s[(nt*GHH + 1)*SPP + m1];
        float slo_a = (tig < 3) ? s0a : s1a;
        float slo_b = (tig < 3) ? s0b : s1b;

        const __half2* mwp = g_mw2 + (size_t)n*6*KPAD;
        float2 mlo_a = __half22float2(mwp[(size_t)tig*KPAD + m0]);
        float2 mlo_b = __half22float2(mwp[(size_t)tig*KPAD + m1]);
        float2 mhi_a = make_float2(0.f, 0.f), mhi_b = make_float2(0.f, 0.f);
        if (tig < 2) {
            mhi_a = __half22float2(mwp[(size_t)(4 + tig)*KPAD + m0]);
            mhi_b = __half22float2(mwp[(size_t)(4 + tig)*KPAD + m1]);
        }

        __half2 a0h = __floats2half2_rn(fmaxf(slo_a*mlo_a.x, 0.f), fmaxf(slo_a*mlo_a.y, 0.f));
        __half2 a1h = __floats2half2_rn(fmaxf(slo_b*mlo_b.x, 0.f), fmaxf(slo_b*mlo_b.y, 0.f));
        __half2 a2h = __floats2half2_rn(fmaxf(s1a*mhi_a.x, 0.f),  fmaxf(s1a*mhi_a.y, 0.f));
        __half2 a3h = __floats2half2_rn(fmaxf(s1b*mhi_b.x, 0.f),  fmaxf(s1b*mhi_b.y, 0.f));
        uint32_t a0 = *(uint32_t*)&a0h, a1 = *(uint32_t*)&a1h;
        uint32_t a2 = *(uint32_t*)&a2h, a3 = *(uint32_t*)&a3h;

        float c0[4] = {0.f,0.f,0.f,0.f};
        float c1[4] = {0.f,0.f,0.f,0.f};
        mma16816h(c0, a0, a1, a2, a3, wf[0][0], wf[0][1]);
        mma16816h(c1, a0, a1, a2, a3, wf[1][0], wf[1][1]);

        {
            int hp = tig*2;
            float* Lb = &L_s[(nt*HHH + hp)*SPP];
            Lb[m0]        = c0[0] + hb_s[hp];
            Lb[SPP + m0]  = c0[1] + hb_s[hp+1];
            Lb[m1]        = c0[2] + hb_s[hp];
            Lb[SPP + m1]  = c0[3] + hb_s[hp+1];
        }
        if (tig < 2) {
            int hp = 8 + tig*2;
            float* Lb = &L_s[(nt*HHH + hp)*SPP];
            Lb[m0]        = c1[0] + hb_s[hp];
            Lb[SPP + m0]  = c1[1] + hb_s[hp+1];
            Lb[m1]        = c1[2] + hb_s[hp];
            Lb[SPP + m1]  = c1[3] + hb_s[hp+1];
        }
    }
    __syncthreads();

    // Phase 2: softmax over m, write fp16 probs (K-pad zeroed)
    for (int pair = warp; pair < NT*HHH; pair += 16) {
        int nt = pair / HHH, hp = pair - nt*HHH;
        float* row = &L_s[pair*SPP];
        float mx = -1e30f;
        for (int m = lane; m < NNN; m += 32) mx = fmaxf(mx, row[m]);
        #pragma unroll
        for (int off = 16; off > 0; off >>= 1)
            mx = fmaxf(mx, __shfl_xor_sync(0xffffffffu, mx, off));
        float sum = 0.f;
        for (int m = lane; m < NNN; m += 32) {
            float e = __expf(row[m] - mx);
            row[m] = e;
            sum += e;
        }
        #pragma unroll
        for (int off = 16; off > 0; off >>= 1)
            sum += __shfl_xor_sync(0xffffffffu, sum, off);
        float inv = 1.f / sum;

        __half* op = g_p + ((size_t)(b*HHH + hp)*NPADR + (n0 + nt))*KPAD;
        #pragma unroll
        for (int i = 0; i < KPAD/32; i++) {
            int m = lane + i*32;
            float val = (m < NNN) ? row[m]*inv : 0.f;
            op[m] = __float2half(val);
        }
    }
}

// ---------------- PV kernel (single V term, unchanged) ------------------------
#define PST 40
#define PV_ABYTES (NPADR*PST*2)
#define PV_BBYTES (DD*PST*2)
#define PV_STAGE  (PV_ABYTES + PV_BBYTES)
#define PV_SMEM   (2*PV_STAGE)

__global__ __launch_bounds__(256, 3)
void pv_kernel()
{
    extern __shared__ char psm[];
    const uint32_t sbase = (uint32_t)__cvta_generic_to_shared(psm);
    __half* smh = (__half*)psm;

    const int tid  = threadIdx.x;
    const int lane = tid & 31;
    const int warp = tid >> 5;
    const int bh   = blockIdx.x;
    const int b    = bh / HHH;
    const int h    = bh - b*HHH;

    const __half* Ap = g_p  + (size_t)bh*NPADR*KPAD;
    const __half* Bp = g_vt + (size_t)bh*DD*KPAD;

    float acc[13][4];
    #pragma unroll
    for (int t = 0; t < 13; t++)
        #pragma unroll
        for (int c = 0; c < 4; c++) acc[t][c] = 0.f;

    const int NST = KPAD/32;               // 7 stages

    auto issue = [&](int s) {
        int k0 = s * 32;
        uint32_t buf = sbase + (uint32_t)(s & 1) * PV_STAGE;
        #pragma unroll
        for (int it = 0; it < 4; it++) {
            int c = tid + it*256;
            if (c < NPADR*4) {
                int r = c >> 2, q = c & 3;
                uint32_t ad = buf + (uint32_t)(r*(PST*2) + q*16);
                asm volatile("cp.async.cg.shared.global [%0], [%1], 16;"
                             :: "r"(ad), "l"(Ap + (size_t)r*KPAD + k0 + q*8));
            }
        }
        {
            int r = tid >> 2, q = tid & 3;
            uint32_t bd = buf + PV_ABYTES + (uint32_t)(r*(PST*2) + q*16);
            asm volatile("cp.async.cg.shared.global [%0], [%1], 16;"
                         :: "r"(bd), "l"(Bp + (size_t)r*KPAD + k0 + q*8));
        }
        asm volatile("cp.async.commit_group;" ::: "memory");
    };

    issue(0);

    for (int s = 0; s < NST; s++) {
        if (s + 1 < NST) {
            issue(s + 1);
            asm volatile("cp.async.wait_group 1;" ::: "memory");
        } else {
            asm volatile("cp.async.wait_group 0;" ::: "memory");
        }
        __syncthreads();

        const __half* As = smh + (size_t)(s & 1) * (PV_STAGE/2);
        const __half* Bs = As + PV_ABYTES/2;

        #pragma unroll
        for (int kh = 0; kh < 32; kh += 16) {
            const __half* pb = Bs + (warp*8 + (lane>>2))*PST + kh + (lane&3)*2;
            uint32_t b0 = *(const uint32_t*)(pb);
            uint32_t b1 = *(const uint32_t*)(pb + 8);
            #pragma unroll
            for (int t = 0; t < 13; t++) {
                const __half* pa = As + (t*16 + (lane>>2))*PST + kh + (lane&3)*2;
                uint32_t a0 = *(const uint32_t*)(pa);
                uint32_t a1 = *(const uint32_t*)(pa + 8*PST);
                uint32_t a2 = *(const uint32_t*)(pa + 8);
                uint32_t a3 = *(const uint32_t*)(pa + 8*PST + 8);
                mma16816h(acc[t], a0, a1, a2, a3, b0, b1);
            }
        }
        __syncthreads();
    }

    // epilogue: write fp16 attention output (feeds tgemm<0>)
    const int ch = h*DD + warp*8 + (lane&3)*2;
    #pragma unroll
    for (int t = 0; t < 13; t++) {
        #pragma unroll
        for (int half = 0; half < 2; half++) {
            int ntok = t*16 + (lane>>2) + half*8;
            if (ntok >= NNN) continue;
            size_t off = ((size_t)b*NNN + ntok)*CC + ch;
            __half2 hv;
            hv.x = __float2half(acc[t][half*2 + 0]);
            hv.y = __float2half(acc[t][half*2 + 1]);
            *(__half2*)(g_a16 + off) = hv;
        }
    }
}

// ---------------- launcher ----------------------------------------------------
extern "C" void kernel_launch(void* const* d_in, const int* in_sizes, int n_in,
                              void* d_out, int out_size)
{
    const float* x         = (const float*)d_in[0];
    const float* qkv_w     = (const float*)d_in[1];
    const float* qkv_b     = (const float*)d_in[2];
    const float* masks     = (const float*)d_in[3];
    const float* mask_proj = (const float*)d_in[4];
    const float* mask_base = (const float*)d_in[5];
    const float* hpw       = (const float*)d_in[6];
    const float* hpb       = (const float*)d_in[7];
    const float* proj_w    = (const float*)d_in[8];
    const float* proj_b    = (const float*)d_in[9];
    float* out             = (float*)d_out;

    void *x16_p, *a16_p, *qw16_p, *pw16_p;
    cudaGetSymbolAddress(&x16_p,  g_x16);
    cudaGetSymbolAddress(&a16_p,  g_a16);
    cudaGetSymbolAddress(&qw16_p, g_qw16);
    cudaGetSymbolAddress(&pw16_p, g_pw16);

    cudaFuncSetAttribute(attn_probs, cudaFuncAttributeMaxDynamicSharedMemorySize,
                         PR_SMEM_BYTES);
    cudaFuncSetAttribute(pv_kernel, cudaFuncAttributeMaxDynamicSharedMemorySize,
                         PV_SMEM);
    cudaFuncSetAttribute(tgemm<0>, cudaFuncAttributeMaxDynamicSharedMemorySize, TG4_SMEM);
    cudaFuncSetAttribute(tgemm<1>, cudaFuncAttributeMaxDynamicSharedMemorySize, TG4_SMEM);

    const int M = MROWS;
    const int MT = (M + TGM - 1)/TGM;

    // 0) fp16 conversions
    tohalf_kernel<<<(M*CC + 255)/256, 256>>>(x, (__half*)x16_p, M*CC);
    wtrans_kernel<<<(CC*QKVN + 255)/256, 256>>>(qkv_w, (__half*)qw16_p, CC, QKVN);
    wtrans_kernel<<<(CC*CC + 255)/256, 256>>>(proj_w, (__half*)pw16_p, CC, CC);
    // 1) QKV GEMM (fp16 single-term) + scatter (q,k fp32; v -> g_vt fp16^T)
    {
        dim3 grid(QKVN/TGN, MT);
        tgemm<1><<<grid, 256, TG4_SMEM>>>((const __half*)x16_p, (const __half*)qw16_p,
                                          qkv_b, nullptr, M, QKVN, CC);
    }
    // 2) mask weights (half2-pair transposed layout)
    mw_kernel<<<(NNN*KPAD + 255)/256, 256>>>(masks, mask_proj, mask_base);
    // 3) probs -> g_p fp16  (NT=8, 512 threads)
    {
        dim3 grid((NNN + NT - 1)/NT, BB);
        attn_probs<<<grid, 512, PR_SMEM_BYTES>>>(hpw, hpb);
    }
    // 4) PV -> g_a16
    pv_kernel<<<BB*HHH, 256, PV_SMEM>>>();
    // 5) output projection (fp16 single-term)
    {
        dim3 grid(CC/TGN, MT);
        tgemm<0><<<grid, 256, TG4_SMEM>>>((const __half*)a16_p, (const __half*)pw16_p,
                                          proj_b, out, M, CC, CC);
    }
}